// round 12
// baseline (speedup 1.0000x reference)
#include <cuda_runtime.h>
#include <cstdint>

// sbvr decode:
//   out[g*16 + l] = sum_s coeff_cache[coeff_idx[g]][s] * ((bvr[g][s] >> l) & 1)
// G = 4,194,304 groups, S = 4, L = 16.
//
// R10 -> R11: L1 wavefronts are the wall (72% across every occupancy/depth
// variant; gather = 8 lines/warp-iter at the 2.07cyc within-LDG replay rate
// ~= 16.6 of ~25.6 L1-cyc). Fix: split the scattered gather LDG.128 into 8
// PREDICATED LDGs -- LDG #k active only on quad k, whose 4 lanes share one
// address -> each LDG touches exactly ONE 128B line -> 8 cross-LDG wavefronts
// @1.0 cyc instead of 8 replays @2.07. Disjoint-predicate same-dest loads are
// the standard ptxas divergent-hammock pattern (no inter-load waits).
// Skeleton = R6 (best): block-contiguous immediate-offset addressing, ITER=8,
// PF=2, pipe-balanced asm decode, __launch_bounds__(256,6).

static constexpr unsigned QT_TOTAL = 16u * 1024u * 1024u;  // 4M groups * 4 quarters
static constexpr int      BLOCK    = 256;
static constexpr int      ITER     = 8;                    // quarter-groups per thread
static constexpr int      PF       = 2;                    // idx/bvr prefetch distance
static constexpr unsigned BLOCKS   = QT_TOTAL / (BLOCK * ITER);  // 8192
static constexpr int      GSTRIDE  = BLOCK / 4;            // 64 groups per iteration

// Gather one 16B coeff row per quad via 8 single-line predicated loads.
// Each lane's row is written by exactly one of the 8 loads (qid in 0..7).
__device__ __forceinline__ float4 gather8(const float4* addr, unsigned qid)
{
    float4 c;
    asm("{\n\t"
        ".reg .pred p;\n\t"
        "setp.eq.u32 p, %4, 0;\n\t@p ld.global.nc.v4.f32 {%0,%1,%2,%3}, [%5];\n\t"
        "setp.eq.u32 p, %4, 1;\n\t@p ld.global.nc.v4.f32 {%0,%1,%2,%3}, [%5];\n\t"
        "setp.eq.u32 p, %4, 2;\n\t@p ld.global.nc.v4.f32 {%0,%1,%2,%3}, [%5];\n\t"
        "setp.eq.u32 p, %4, 3;\n\t@p ld.global.nc.v4.f32 {%0,%1,%2,%3}, [%5];\n\t"
        "setp.eq.u32 p, %4, 4;\n\t@p ld.global.nc.v4.f32 {%0,%1,%2,%3}, [%5];\n\t"
        "setp.eq.u32 p, %4, 5;\n\t@p ld.global.nc.v4.f32 {%0,%1,%2,%3}, [%5];\n\t"
        "setp.eq.u32 p, %4, 6;\n\t@p ld.global.nc.v4.f32 {%0,%1,%2,%3}, [%5];\n\t"
        "setp.eq.u32 p, %4, 7;\n\t@p ld.global.nc.v4.f32 {%0,%1,%2,%3}, [%5];\n\t"
        "}"
        : "=f"(c.x), "=f"(c.y), "=f"(c.z), "=f"(c.w)
        : "r"(qid), "l"(addr));
    return c;
}

// Pipe-balanced decode: lop3 with predicate output (ALU; AND+test in one op)
// feeding predicated add.f32 (FMA pipe). Exact fp32 -> rel_err 0.
__device__ __forceinline__ float4 decode_quarter(int4 w, float4 c, unsigned m0)
{
    float4 r;
    asm(
    "{\n\t"
    ".reg .pred q, p0, p1, p2, p3;\n\t"
    ".reg .b32  t, m1, m2, m3;\n\t"
    "setp.ne.u32 q, %4, %4;\n\t"
    "shl.b32 m1, %8, 1;\n\t"
    "shl.b32 m2, %8, 2;\n\t"
    "shl.b32 m3, %8, 3;\n\t"
    // ---- element 0 ----
    "lop3.or.b32 t|p0, %4, %8, %4, 0xC0, q;\n\t"
    "lop3.or.b32 t|p1, %5, %8, %5, 0xC0, q;\n\t"
    "lop3.or.b32 t|p2, %6, %8, %6, 0xC0, q;\n\t"
    "lop3.or.b32 t|p3, %7, %8, %7, 0xC0, q;\n\t"
    "selp.f32 %0, %9, 0f00000000, p0;\n\t"
    "@p1 add.rn.f32 %0, %0, %10;\n\t"
    "@p2 add.rn.f32 %0, %0, %11;\n\t"
    "@p3 add.rn.f32 %0, %0, %12;\n\t"
    // ---- element 1 ----
    "lop3.or.b32 t|p0, %4, m1, %4, 0xC0, q;\n\t"
    "lop3.or.b32 t|p1, %5, m1, %5, 0xC0, q;\n\t"
    "lop3.or.b32 t|p2, %6, m1, %6, 0xC0, q;\n\t"
    "lop3.or.b32 t|p3, %7, m1, %7, 0xC0, q;\n\t"
    "selp.f32 %1, %9, 0f00000000, p0;\n\t"
    "@p1 add.rn.f32 %1, %1, %10;\n\t"
    "@p2 add.rn.f32 %1, %1, %11;\n\t"
    "@p3 add.rn.f32 %1, %1, %12;\n\t"
    // ---- element 2 ----
    "lop3.or.b32 t|p0, %4, m2, %4, 0xC0, q;\n\t"
    "lop3.or.b32 t|p1, %5, m2, %5, 0xC0, q;\n\t"
    "lop3.or.b32 t|p2, %6, m2, %6, 0xC0, q;\n\t"
    "lop3.or.b32 t|p3, %7, m2, %7, 0xC0, q;\n\t"
    "selp.f32 %2, %9, 0f00000000, p0;\n\t"
    "@p1 add.rn.f32 %2, %2, %10;\n\t"
    "@p2 add.rn.f32 %2, %2, %11;\n\t"
    "@p3 add.rn.f32 %2, %2, %12;\n\t"
    // ---- element 3 ----
    "lop3.or.b32 t|p0, %4, m3, %4, 0xC0, q;\n\t"
    "lop3.or.b32 t|p1, %5, m3, %5, 0xC0, q;\n\t"
    "lop3.or.b32 t|p2, %6, m3, %6, 0xC0, q;\n\t"
    "lop3.or.b32 t|p3, %7, m3, %7, 0xC0, q;\n\t"
    "selp.f32 %3, %9, 0f00000000, p0;\n\t"
    "@p1 add.rn.f32 %3, %3, %10;\n\t"
    "@p2 add.rn.f32 %3, %3, %11;\n\t"
    "@p3 add.rn.f32 %3, %3, %12;\n\t"
    "}\n\t"
    : "=f"(r.x), "=f"(r.y), "=f"(r.z), "=f"(r.w)
    : "r"(w.x), "r"(w.y), "r"(w.z), "r"(w.w),
      "r"(m0),
      "f"(c.x), "f"(c.y), "f"(c.z), "f"(c.w));
    return r;
}

__global__ __launch_bounds__(BLOCK, 6) void sbvr_kernel(
    const float4* __restrict__ coeff_cache,   // [65536] rows of 4 floats
    const int*    __restrict__ coeff_idx,     // [G]
    const int4*   __restrict__ bvr,           // [G]
    float4*       __restrict__ out)           // [4*G]
{
    // Block-contiguous tile: quarter-indices [b*BLOCK*ITER, ...), iteration i
    // at +i*BLOCK. All per-iteration offsets are small immediates.
    unsigned t = blockIdx.x * (unsigned)(BLOCK * ITER) + threadIdx.x;
    unsigned g = t >> 2;

    const int*  ip = coeff_idx + g;
    const int4* wp = bvr + g;
    float4*     op = out + t;

    unsigned m0  = 1u << ((t & 3u) * 4u);  // BLOCK % 4 == 0: invariant over i
    unsigned qid = (threadIdx.x >> 2) & 7u; // quad id within warp (0..7)

    int  ci[ITER];
    int4 w [ITER];

    // Prologue: idx+bvr for iterations 0..PF-1.
    #pragma unroll
    for (int i = 0; i < PF; i++) {
        ci[i] = __ldcs(ip + i * GSTRIDE);
        w [i] = __ldcs(wp + i * GSTRIDE);
    }
    float4 c_cur = gather8(coeff_cache + ci[0], qid);  // gather for iteration 0

    #pragma unroll
    for (int i = 0; i < ITER; i++) {
        if (i + PF < ITER) {                    // static: no clamps
            ci[i + PF] = __ldcs(ip + (i + PF) * GSTRIDE);
            w [i + PF] = __ldcs(wp + (i + PF) * GSTRIDE);
        }
        float4 c_nxt = c_cur;
        if (i + 1 < ITER)                       // gather one iteration ahead
            c_nxt = gather8(coeff_cache + ci[i + 1], qid);

        float4 r = decode_quarter(w[i], c_cur, m0);
        __stcs(op + i * BLOCK, r);

        c_cur = c_nxt;
    }
}

extern "C" void kernel_launch(void* const* d_in, const int* in_sizes, int n_in,
                              void* d_out, int out_size)
{
    const float4* coeff_cache = (const float4*)d_in[0];  // [65536,4] f32
    const int*    coeff_idx   = (const int*)d_in[1];     // [G] i32
    const int4*   bvr         = (const int4*)d_in[2];    // [G,4] i32
    float4*       out         = (float4*)d_out;          // [8192,8192] f32

    (void)in_sizes; (void)n_in; (void)out_size;

    sbvr_kernel<<<BLOCKS, BLOCK>>>(coeff_cache, coeff_idx, bvr, out);
}

// round 13
// speedup vs baseline: 2.3161x; 2.3161x over previous
#include <cuda_runtime.h>
#include <cstdint>

// sbvr decode:
//   out[g*16 + l] = sum_s coeff_cache[coeff_idx[g]][s] * ((bvr[g][s] >> l) & 1)
// G = 4,194,304 groups, S = 4, L = 16.
//
// R12 -> R13: revert the serialized predicated-gather (WAW chain -> 143us).
// New lever: kill the 4x quad duplication on bvr and coeff returns.
// Lane (quad q, slot s) loads ONLY word s: bvr scalar stream becomes fully
// contiguous (1 line/warp vs 1 line + 4x return), coeff gather returns 128B
// instead of 512B (same 8-line replay cost - that part is irreducible).
// Decode runs 4 rounds: round r uses the quad-rotated (w,c) pair obtained via
// 2 shfl.idx; accumulate is the proven lop3-pred + @p add.rn.f32 mix.
// Skeleton = R6 (best: 61.9us): block-contiguous immediate offsets, ITER=8,
// PF=2, gather distance 1, __launch_bounds__(256,6), __ldcs/__ldg/__stcs.

static constexpr unsigned QT_TOTAL = 16u * 1024u * 1024u;  // 4M groups * 4 quarters
static constexpr int      BLOCK    = 256;
static constexpr int      ITER     = 8;                    // quarter-groups per thread
static constexpr int      PF       = 2;                    // idx/bvr prefetch distance
static constexpr unsigned BLOCKS   = QT_TOTAL / (BLOCK * ITER);  // 8192
static constexpr int      GSTRIDE  = BLOCK / 4;            // 64 groups per iteration

// Round 0: r_j = (w & m0<<j) ? c : 0   (4 lop3-pred + 4 selp)
__device__ __forceinline__ float4 round0(unsigned w, float c, unsigned m0)
{
    float4 r;
    asm("{\n\t"
        ".reg .pred q, p0, p1, p2, p3;\n\t"
        ".reg .b32  t, m1, m2, m3;\n\t"
        "setp.ne.u32 q, %4, %4;\n\t"
        "shl.b32 m1, %5, 1;\n\t"
        "shl.b32 m2, %5, 2;\n\t"
        "shl.b32 m3, %5, 3;\n\t"
        "lop3.or.b32 t|p0, %4, %5, %4, 0xC0, q;\n\t"
        "lop3.or.b32 t|p1, %4, m1, %4, 0xC0, q;\n\t"
        "lop3.or.b32 t|p2, %4, m2, %4, 0xC0, q;\n\t"
        "lop3.or.b32 t|p3, %4, m3, %4, 0xC0, q;\n\t"
        "selp.f32 %0, %6, 0f00000000, p0;\n\t"
        "selp.f32 %1, %6, 0f00000000, p1;\n\t"
        "selp.f32 %2, %6, 0f00000000, p2;\n\t"
        "selp.f32 %3, %6, 0f00000000, p3;\n\t"
        "}"
        : "=f"(r.x), "=f"(r.y), "=f"(r.z), "=f"(r.w)
        : "r"(w), "r"(m0), "f"(c));
    return r;
}

// Rounds 1..3: r_j += (w & m0<<j) ? c : 0   (4 lop3-pred + 4 @p add)
__device__ __forceinline__ void accum(float4& r, unsigned w, float c, unsigned m0)
{
    asm("{\n\t"
        ".reg .pred q, p0, p1, p2, p3;\n\t"
        ".reg .b32  t, m1, m2, m3;\n\t"
        "setp.ne.u32 q, %4, %4;\n\t"
        "shl.b32 m1, %5, 1;\n\t"
        "shl.b32 m2, %5, 2;\n\t"
        "shl.b32 m3, %5, 3;\n\t"
        "lop3.or.b32 t|p0, %4, %5, %4, 0xC0, q;\n\t"
        "lop3.or.b32 t|p1, %4, m1, %4, 0xC0, q;\n\t"
        "lop3.or.b32 t|p2, %4, m2, %4, 0xC0, q;\n\t"
        "lop3.or.b32 t|p3, %4, m3, %4, 0xC0, q;\n\t"
        "@p0 add.rn.f32 %0, %0, %6;\n\t"
        "@p1 add.rn.f32 %1, %1, %6;\n\t"
        "@p2 add.rn.f32 %2, %2, %6;\n\t"
        "@p3 add.rn.f32 %3, %3, %6;\n\t"
        "}"
        : "+f"(r.x), "+f"(r.y), "+f"(r.z), "+f"(r.w)
        : "r"(w), "r"(m0), "f"(c));
}

__global__ __launch_bounds__(BLOCK, 6) void sbvr_kernel(
    const float4* __restrict__ coeff_cache,   // [65536] rows of 4 floats
    const int*    __restrict__ coeff_idx,     // [G]
    const int4*   __restrict__ bvr,           // [G]
    float4*       __restrict__ out)           // [4*G]
{
    // Quarter index t: group g = t>>2, slot/element-range s = t&3.
    // Key identity: bvr word index g*4 + s == t  -> scalar bvr stream is
    // exactly the quarter-index stream (fully contiguous per warp).
    unsigned t    = blockIdx.x * (unsigned)(BLOCK * ITER) + threadIdx.x;
    unsigned lane = threadIdx.x & 31u;
    unsigned sid  = t & 3u;

    const int*   ip = coeff_idx + (t >> 2);
    const int*   wp = (const int*)bvr + t;          // scalar word stream
    const float* cp = (const float*)coeff_cache;    // scalar coeff table
    float4*      op = out + t;

    unsigned m0  = 1u << (sid * 4u);                 // invariant over i
    unsigned rot = (lane & 28u) | ((lane + 1u) & 3u); // quad rotate-by-1

    int ci[ITER];
    int ws[ITER];

    // Prologue: idx + scalar bvr for iterations 0..PF-1.
    #pragma unroll
    for (int i = 0; i < PF; i++) {
        ci[i] = __ldcs(ip + i * GSTRIDE);
        ws[i] = __ldcs(wp + i * BLOCK);
    }
    float c_cur = __ldg(cp + (unsigned)ci[0] * 4u + sid);  // gather iter 0

    #pragma unroll
    for (int i = 0; i < ITER; i++) {
        if (i + PF < ITER) {                    // static: no clamps
            ci[i + PF] = __ldcs(ip + (i + PF) * GSTRIDE);
            ws[i + PF] = __ldcs(wp + (i + PF) * BLOCK);
        }
        float c_nxt = c_cur;
        if (i + 1 < ITER)                       // gather one iteration ahead
            c_nxt = __ldg(cp + (unsigned)ci[i + 1] * 4u + sid);

        // Decode: own (w,c) pair, then 3 quad-rotations cover all 4 sums.
        unsigned wv = (unsigned)ws[i];
        float    cv = c_cur;
        float4 r = round0(wv, cv, m0);
        #pragma unroll
        for (int rr = 0; rr < 3; rr++) {
            wv = __shfl_sync(0xffffffffu, wv, rot);
            cv = __shfl_sync(0xffffffffu, cv, rot);
            accum(r, wv, cv, m0);
        }

        __stcs(op + i * BLOCK, r);
        c_cur = c_nxt;
    }
}

extern "C" void kernel_launch(void* const* d_in, const int* in_sizes, int n_in,
                              void* d_out, int out_size)
{
    const float4* coeff_cache = (const float4*)d_in[0];  // [65536,4] f32
    const int*    coeff_idx   = (const int*)d_in[1];     // [G] i32
    const int4*   bvr         = (const int4*)d_in[2];    // [G,4] i32
    float4*       out         = (float4*)d_out;          // [8192,8192] f32

    (void)in_sizes; (void)n_in; (void)out_size;

    sbvr_kernel<<<BLOCKS, BLOCK>>>(coeff_cache, coeff_idx, bvr, out);
}